// round 14
// baseline (speedup 1.0000x reference)
#include <cuda_runtime.h>
#include <cuda_fp16.h>
#include <math.h>

// Problem constants
#define Bn 2
#define Tn 1024
#define Cn 2048
#define Hn 32
#define Nn 64
#define BTn (Bn*Tn)

// ------------------------- scratch (static device globals) -------------------------
__device__ __half g_xr[BTn*Cn];
__device__ __half g_xw[BTn*Cn];
__device__ __half g_xk[BTn*Cn];
__device__ __half g_xv[BTn*Cn];
__device__ __half g_xa[BTn*Cn];
__device__ __half g_xg[BTn*Cn];
__device__ float g_r [BTn*Cn];
__device__ float g_k [BTn*Cn];
__device__ float g_v [BTn*Cn];
__device__ float g_w [BTn*Cn];
__device__ float g_za[BTn*Cn];
__device__ float g_zv[BTn*Cn];
__device__ float g_g [BTn*Cn];
__device__ float g_y [BTn*Cn];
__device__ __half g_op[BTn*Cn];
__device__ __half g_tw[BTn*128];
__device__ __half g_ta[BTn*128];
__device__ __half g_tv[BTn*64];
__device__ __half g_tg[BTn*256];
// packed scan operands: [B*H][T][6*64]  order: r,w,k,v,ah,bh
__device__ float g_pack[(size_t)Bn*Hn*Tn*384];
// half2-packed weights: [K/2][N] u32
__device__ unsigned g_Wrp[(Cn/2)*Cn];
__device__ unsigned g_Wkp[(Cn/2)*Cn];
__device__ unsigned g_Wvp[(Cn/2)*Cn];
__device__ unsigned g_Wop[(Cn/2)*Cn];
__device__ unsigned g_w1p[(Cn/2)*128];
__device__ unsigned g_a1p[(Cn/2)*128];
__device__ unsigned g_v1p[(Cn/2)*64];
__device__ unsigned g_g1p[(Cn/2)*256];
__device__ unsigned g_w2p[64*Cn];
__device__ unsigned g_a2p[64*Cn];
__device__ unsigned g_v2p[32*Cn];
__device__ unsigned g_g2p[128*Cn];

// ------------------------- helpers -------------------------
__device__ __forceinline__ void mma_h(float* d, const unsigned* a, const unsigned* b) {
    asm volatile(
        "mma.sync.aligned.m16n8k16.row.col.f32.f16.f16.f32 "
        "{%0,%1,%2,%3}, {%4,%5,%6,%7}, {%8,%9}, {%0,%1,%2,%3};"
        : "+f"(d[0]), "+f"(d[1]), "+f"(d[2]), "+f"(d[3])
        : "r"(a[0]), "r"(a[1]), "r"(a[2]), "r"(a[3]),
          "r"(b[0]), "r"(b[1]));
}

__device__ __forceinline__ void cp16(void* smem, const void* g) {
    unsigned saddr = (unsigned)__cvta_generic_to_shared(smem);
    asm volatile("cp.async.cg.shared.global [%0], [%1], 16;" :: "r"(saddr), "l"(g));
}
__device__ __forceinline__ void cp_commit() { asm volatile("cp.async.commit_group;" ::: "memory"); }
__device__ __forceinline__ void cp_wait1()  { asm volatile("cp.async.wait_group 1;" ::: "memory"); }

__device__ __forceinline__ float warp_sum(float v) {
#pragma unroll
    for (int o = 16; o > 0; o >>= 1) v += __shfl_xor_sync(0xffffffffu, v, o);
    return v;
}

__device__ __forceinline__ unsigned pack_h2(float lo, float hi) {
    __half2 h = __halves2half2(__float2half_rn(lo), __float2half_rn(hi));
    return *(unsigned*)&h;
}

// ------------------------- weight pack prepass (float -> half2-along-k) ------------
struct WP {
    const float* src[12];
    unsigned* dst[12];
    int K2d[12], Nd[12], Ks[12], Ns[12];
};
__global__ void pack_w(WP p) {
    int z = blockIdx.y;
    int i = blockIdx.x * blockDim.x + threadIdx.x;
    int tot = p.K2d[z] * p.Nd[z];
    if (i >= tot) return;
    int k2 = i / p.Nd[z], n = i % p.Nd[z];
    int k0 = 2 * k2, k1 = k0 + 1;
    float lo = 0.f, hi = 0.f;
    if (n < p.Ns[z]) {
        if (k0 < p.Ks[z]) lo = p.src[z][(size_t)k0 * p.Ns[z] + n];
        if (k1 < p.Ks[z]) hi = p.src[z][(size_t)k1 * p.Ns[z] + n];
    }
    p.dst[z][i] = pack_h2(lo, hi);
}

// ------------------------- batched 3-stage fp16 GEMM (m16n8k16, f32 accum) ---------
struct GH {
    const __half* A[4];
    const unsigned* Bp[4];
    void* C[4];
    int N[4];
    int K[4];
    int act[4];      // 0=none 1=tanh 2=sigmoid
    int outHalf[4];
};

template<int BM, int BN, int WM, int WN>
__global__ void __launch_bounds__((BM/WM)*(BN/WN)*32)
gemm_h(GH p) {
    constexpr int KT = 32;
    constexpr int KT2 = 16;
    constexpr int STG = 3;
    constexpr int WARPS_M = BM / WM;
    constexpr int WARPS_N = BN / WN;
    constexpr int NTHREADS = WARPS_M * WARPS_N * 32;
    constexpr int MT = WM / 16;
    constexpr int NT_ = WN / 8;
    constexpr int ASTR = KT2 + 4;
    constexpr int BSTR = BN + 8;

    extern __shared__ unsigned dsmg[];
    unsigned (*Asm)[BM][ASTR] = (unsigned(*)[BM][ASTR])dsmg;
    unsigned (*Bsm)[KT2][BSTR] = (unsigned(*)[KT2][BSTR])(dsmg + STG * BM * ASTR);

    const int z = blockIdx.z;
    const __half* A = p.A[z];
    const unsigned* B = p.Bp[z];
    const int N = p.N[z], K = p.K[z], act = p.act[z], oh = p.outHalf[z];
    const int bn = blockIdx.x * BN;
    if (bn >= N) return;
    const int bm = blockIdx.y * BM;

    const int tid = threadIdx.x;
    const int wid = tid >> 5, lane = tid & 31;
    const int gid = lane >> 2, tig = lane & 3;
    const int warp_m = wid / WARPS_N, warp_n = wid % WARPS_N;
    const int wm = warp_m * WM, wn = warp_n * WN;

    float acc[MT][NT_][4];
#pragma unroll
    for (int i = 0; i < MT; i++)
#pragma unroll
        for (int j = 0; j < NT_; j++)
#pragma unroll
            for (int q = 0; q < 4; q++) acc[i][j][q] = 0.f;

    auto load_stage = [&](int s, int kt) {
#pragma unroll
        for (int i = 0; i < (BM * 4) / NTHREADS; i++) {
            int id = tid + i * NTHREADS;
            int m = id >> 2, q = (id & 3) * 4;
            cp16(&Asm[s][m][q], A + (size_t)(bm + m) * K + kt * KT + q * 2);
        }
#pragma unroll
        for (int i = 0; i < (KT2 * BN / 4) / NTHREADS; i++) {
            int id = tid + i * NTHREADS;
            int kr = id / (BN / 4), nq = (id % (BN / 4)) * 4;
            cp16(&Bsm[s][kr][nq], B + (size_t)(kt * KT2 + kr) * N + bn + nq);
        }
    };

    const int nk = K / KT;
    load_stage(0, 0); cp_commit();
    load_stage(1, 1); cp_commit();

    int s = 0;
    for (int kt = 0; kt < nk; kt++) {
        cp_wait1();
        __syncthreads();
        if (kt + 2 < nk) load_stage((kt + 2) % STG, kt + 2);
        cp_commit();

#pragma unroll
        for (int kk2 = 0; kk2 < KT2; kk2 += 8) {
            unsigned af[MT][4], bf[NT_][2];
#pragma unroll
            for (int mt = 0; mt < MT; mt++) {
                int rm = wm + mt * 16 + gid;
                af[mt][0] = Asm[s][rm][kk2 + tig];
                af[mt][1] = Asm[s][rm + 8][kk2 + tig];
                af[mt][2] = Asm[s][rm][kk2 + tig + 4];
                af[mt][3] = Asm[s][rm + 8][kk2 + tig + 4];
            }
#pragma unroll
            for (int nt = 0; nt < NT_; nt++) {
                int cn = wn + nt * 8 + gid;
                bf[nt][0] = Bsm[s][kk2 + tig][cn];
                bf[nt][1] = Bsm[s][kk2 + tig + 4][cn];
            }
#pragma unroll
            for (int mt = 0; mt < MT; mt++)
#pragma unroll
                for (int nt = 0; nt < NT_; nt++)
                    mma_h(acc[mt][nt], af[mt], bf[nt]);
        }
        s = (s + 1 == STG) ? 0 : s + 1;
    }

#pragma unroll
    for (int mt = 0; mt < MT; mt++) {
#pragma unroll
        for (int nt = 0; nt < NT_; nt++) {
            int r0 = bm + wm + mt * 16 + gid;
            int c = bn + wn + nt * 8 + tig * 2;
            float v0 = acc[mt][nt][0], v1 = acc[mt][nt][1];
            float v2 = acc[mt][nt][2], v3 = acc[mt][nt][3];
            if (act == 1) {
                v0 = tanhf(v0); v1 = tanhf(v1); v2 = tanhf(v2); v3 = tanhf(v3);
            } else if (act == 2) {
                v0 = 1.f / (1.f + expf(-v0)); v1 = 1.f / (1.f + expf(-v1));
                v2 = 1.f / (1.f + expf(-v2)); v3 = 1.f / (1.f + expf(-v3));
            }
            if (oh) {
                __half* C = (__half*)p.C[z];
                *(unsigned*)(C + (size_t)r0 * N + c) = pack_h2(v0, v1);
                *(unsigned*)(C + (size_t)(r0 + 8) * N + c) = pack_h2(v2, v3);
            } else {
                float* C = (float*)p.C[z];
                *(float2*)(C + (size_t)r0 * N + c) = make_float2(v0, v1);
                *(float2*)(C + (size_t)(r0 + 8) * N + c) = make_float2(v2, v3);
            }
        }
    }
}

// ------------------------- token shift + 6 mixes (half outputs) --------------------
__global__ void mix_kernel(const float4* __restrict__ x,
                           const float4* __restrict__ cr, const float4* __restrict__ cw,
                           const float4* __restrict__ ck, const float4* __restrict__ cv,
                           const float4* __restrict__ ca, const float4* __restrict__ cg) {
    size_t i = (size_t)blockIdx.x * blockDim.x + threadIdx.x;
    constexpr size_t TOT = (size_t)BTn * Cn / 4;
    constexpr int C4 = Cn / 4;
    if (i >= TOT) return;
    int c = (int)(i % C4);
    size_t bt = i / C4;
    int t = (int)(bt % Tn);
    float4 xc = x[i];
    float4 prev = (t == 0) ? make_float4(0.f, 0.f, 0.f, 0.f) : x[i - C4];
    float4 dx = make_float4(prev.x - xc.x, prev.y - xc.y, prev.z - xc.z, prev.w - xc.w);
#define MIXO(dst, coef) { \
    float4 cc = coef[c]; \
    uint2 o; \
    o.x = pack_h2(fmaf(dx.x, cc.x, xc.x), fmaf(dx.y, cc.y, xc.y)); \
    o.y = pack_h2(fmaf(dx.z, cc.z, xc.z), fmaf(dx.w, cc.w, xc.w)); \
    ((uint2*)dst)[i] = o; }
    MIXO(g_xr, cr); MIXO(g_xw, cw); MIXO(g_xk, ck);
    MIXO(g_xv, cv); MIXO(g_xa, ca); MIXO(g_xg, cg);
#undef MIXO
}

// ------------------------- per-head elementwise stage 2 (warp per head) -----------
__global__ void __launch_bounds__(256) ew2_kernel(
        const float* __restrict__ w0, const float* __restrict__ a0,
        const float* __restrict__ v0, const float* __restrict__ kkw,
        const float* __restrict__ kaw, const float* __restrict__ vfirst) {
    int w = blockIdx.x * 8 + (threadIdx.x >> 5);
    int lane = threadIdx.x & 31;
    int bt = w / Hn, h = w % Hn;
    int b = bt / Tn, t = bt % Tn;
    size_t pb = ((size_t)(b * Hn + h) * Tn + t) * 384;
    size_t base = (size_t)bt * Cn + h * Nn;

    float kraw[2], kkp[2], av[2], vv[2], wv[2];
#pragma unroll
    for (int j = 0; j < 2; j++) {
        int n = lane + 32 * j;
        int c = h * Nn + n;
        size_t idx = base + n;
        kraw[j] = g_k[idx];
        kkp[j] = kraw[j] * kkw[c];
        av[j] = 1.f / (1.f + expf(-(a0[c] + g_za[idx])));
        float xw = -(w0[c] + g_w[idx]);
        float sp = (xw > 20.f) ? xw : log1pf(expf(xw));
        wv[j] = expf(-expf(-0.5f - sp));
        float vs = 1.f / (1.f + expf(-(v0[c] + g_zv[idx])));
        float vraw = g_v[idx];
        vv[j] = vraw + (vfirst[idx] - vraw) * vs;
    }
    float nrm2 = warp_sum(kkp[0] * kkp[0] + kkp[1] * kkp[1]);
    float inv = 1.f / fmaxf(sqrtf(nrm2), 1e-12f);

#pragma unroll
    for (int j = 0; j < 2; j++) {
        int n = lane + 32 * j;
        int c = h * Nn + n;
        size_t idx = base + n;
        float kkn = kkp[j] * inv;
        g_pack[pb +       n] = g_r[idx];
        g_pack[pb +  64 + n] = wv[j];
        g_pack[pb + 128 + n] = kraw[j] * (1.f + (av[j] - 1.f) * kaw[c]);
        g_pack[pb + 192 + n] = vv[j];
        g_pack[pb + 256 + n] = -kkn;
        g_pack[pb + 320 + n] = kkn * av[j];
    }
}

// ------------------------- WKV7 scan: 256 threads, 8 k's/thread, 8-step groups -----
// grid = 2*B*H blocks. Block handles v in [vh*32, vh*32+32).
// Thread (v_local = tid>>3, kq = tid&7) owns S[v][8*kq .. 8*kq+7].
__global__ void __launch_bounds__(256) wkv7_scan() {
    const int bh = blockIdx.x >> 1;
    const int vh = blockIdx.x & 1;
    const int b = bh / Hn, h = bh % Hn;
    const int tid = threadIdx.x;
    const int v_local = tid >> 3;
    const int kq = tid & 7;
    const int v = vh * 32 + v_local;
    constexpr int GS = 8;

    float S[8];
#pragma unroll
    for (int i = 0; i < 8; i++) S[i] = 0.f;

    __shared__ float4 sm4[2][GS][96];
    const float4* pk4 = (const float4*)(g_pack + (size_t)bh * Tn * 384);
    size_t ybase = (size_t)b * Tn * Cn + (size_t)h * Nn + v;

    auto load_group = [&](int buf, int g) {
#pragma unroll
        for (int i = 0; i < (GS * 96) / 256; i++) {
            int id = tid + i * 256;
            int st = id / 96, off = id % 96;
            cp16(&sm4[buf][st][off], pk4 + (size_t)(g * GS + st) * 96 + off);
        }
    };

    load_group(0, 0); cp_commit();
    load_group(1, 1); cp_commit();

    const int kb4 = kq * 2;   // float4 index of this thread's 8-k base
    constexpr int NG = Tn / GS;

    for (int g = 0; g < NG; g++) {
        cp_wait1();
        __syncthreads();
        const int buf = g & 1;

#pragma unroll
        for (int st = 0; st < GS; st++) {
            const float4* r4  = &sm4[buf][st][0  + kb4];
            const float4* w4  = &sm4[buf][st][16 + kb4];
            const float4* k4  = &sm4[buf][st][32 + kb4];
            const float4* ah4 = &sm4[buf][st][64 + kb4];
            const float4* bh4 = &sm4[buf][st][80 + kb4];
            const float vv = ((const float*)&sm4[buf][st][48])[v];

            float4 A0 = ah4[0], A1 = ah4[1];
            float sa0 = S[0] * A0.x, sa1 = S[4] * A1.x;
            sa0 = fmaf(S[1], A0.y, sa0); sa1 = fmaf(S[5], A1.y, sa1);
            sa0 = fmaf(S[2], A0.z, sa0); sa1 = fmaf(S[6], A1.z, sa1);
            sa0 = fmaf(S[3], A0.w, sa0); sa1 = fmaf(S[7], A1.w, sa1);
            float sa = sa0 + sa1;
            sa += __shfl_xor_sync(0xffffffffu, sa, 1);
            sa += __shfl_xor_sync(0xffffffffu, sa, 2);
            sa += __shfl_xor_sync(0xffffffffu, sa, 4);

            float y0 = 0.f, y1 = 0.f;
#pragma unroll
            for (int j = 0; j < 2; j++) {
                float4 W = w4[j], Bv = bh4[j], Kv = k4[j], R = r4[j];
                S[j*4+0] = fmaf(S[j*4+0], W.x, fmaf(sa, Bv.x, vv * Kv.x));
                S[j*4+1] = fmaf(S[j*4+1], W.y, fmaf(sa, Bv.y, vv * Kv.y));
                S[j*4+2] = fmaf(S[j*4+2], W.z, fmaf(sa, Bv.z, vv * Kv.z));
                S[j*4+3] = fmaf(S[j*4+3], W.w, fmaf(sa, Bv.w, vv * Kv.w));
                y0 = fmaf(S[j*4+0], R.x, y0);
                y0 = fmaf(S[j*4+1], R.y, y0);
                y1 = fmaf(S[j*4+2], R.z, y1);
                y1 = fmaf(S[j*4+3], R.w, y1);
            }
            float y = y0 + y1;
            y += __shfl_xor_sync(0xffffffffu, y, 1);
            y += __shfl_xor_sync(0xffffffffu, y, 2);
            y += __shfl_xor_sync(0xffffffffu, y, 4);
            if (kq == 0) g_y[ybase + (size_t)(g * GS + st) * Cn] = y;
        }

        __syncthreads();
        if (g + 2 < NG) load_group(buf, g + 2);
        cp_commit();
    }
}

// ------------------------- groupnorm + rk residual + gate (warp per head) ---------
__global__ void __launch_bounds__(256) gn_kernel(
        const float* __restrict__ r_k, const float* __restrict__ gnw,
        const float* __restrict__ gnb) {
    int w = blockIdx.x * 8 + (threadIdx.x >> 5);
    int lane = threadIdx.x & 31;
    int bt = w / Hn, h = w % Hn;
    int b = bt / Tn, t = bt % Tn;
    size_t pb = ((size_t)(b * Hn + h) * Tn + t) * 384;
    size_t base = (size_t)bt * Cn + h * Nn;

    float yv[2], rr[2], kk[2], vv[2];
#pragma unroll
    for (int j = 0; j < 2; j++) {
        int n = lane + 32 * j;
        yv[j] = g_y[base + n];
        rr[j] = g_pack[pb + n];
        kk[j] = g_pack[pb + 128 + n];
        vv[j] = g_pack[pb + 192 + n];
    }
    float mu = warp_sum(yv[0] + yv[1]) * (1.f / 64.f);
    float d0 = yv[0] - mu, d1 = yv[1] - mu;
    float var = warp_sum(d0 * d0 + d1 * d1) * (1.f / 64.f);
    float rs = rsqrtf(var + (float)(Nn * 1e-5));

    float dp0, dp1;
    {
        int c0 = h * Nn + lane, c1 = c0 + 32;
        dp0 = rr[0] * kk[0] * r_k[c0];
        dp1 = rr[1] * kk[1] * r_k[c1];
    }
    float dot = warp_sum(dp0 + dp1);

#pragma unroll
    for (int j = 0; j < 2; j++) {
        int n = lane + 32 * j;
        int c = h * Nn + n;
        size_t idx = base + n;
        float d = (j == 0) ? d0 : d1;
        float yn = d * rs * gnw[c] + gnb[c];
        g_op[idx] = __float2half_rn((yn + dot * vv[j]) * g_g[idx]);
    }
}

// ------------------------- launch -------------------------
extern "C" void kernel_launch(void* const* d_in, const int* in_sizes, int n_in,
                              void* d_out, int out_size) {
    (void)in_sizes; (void)n_in; (void)out_size;
    const float* x      = (const float*)d_in[0];
    const float* vfirst = (const float*)d_in[1];
    const float* x_r = (const float*)d_in[2];
    const float* x_w = (const float*)d_in[3];
    const float* x_k = (const float*)d_in[4];
    const float* x_v = (const float*)d_in[5];
    const float* x_a = (const float*)d_in[6];
    const float* x_g = (const float*)d_in[7];
    const float* w0  = (const float*)d_in[8];
    const float* w1  = (const float*)d_in[9];
    const float* w2  = (const float*)d_in[10];
    const float* a0  = (const float*)d_in[11];
    const float* a1  = (const float*)d_in[12];
    const float* a2  = (const float*)d_in[13];
    const float* v0  = (const float*)d_in[14];
    const float* v1  = (const float*)d_in[15];
    const float* v2  = (const float*)d_in[16];
    const float* g1  = (const float*)d_in[17];
    const float* g2  = (const float*)d_in[18];
    const float* k_k = (const float*)d_in[19];
    const float* k_a = (const float*)d_in[20];
    const float* r_k = (const float*)d_in[21];
    const float* W_r = (const float*)d_in[22];
    const float* W_k = (const float*)d_in[23];
    const float* W_v = (const float*)d_in[24];
    const float* W_o = (const float*)d_in[25];
    const float* gnw = (const float*)d_in[26];
    const float* gnb = (const float*)d_in[27];
    float* out = (float*)d_out;

#define GETP(T, name, sym) T* name; cudaGetSymbolAddress((void**)&name, sym)
    GETP(__half, p_xr, g_xr); GETP(__half, p_xw, g_xw); GETP(__half, p_xk, g_xk);
    GETP(__half, p_xv, g_xv); GETP(__half, p_xa, g_xa); GETP(__half, p_xg, g_xg);
    GETP(float, p_r, g_r); GETP(float, p_k, g_k); GETP(float, p_v, g_v);
    GETP(float, p_w, g_w); GETP(float, p_za, g_za); GETP(float, p_zv, g_zv);
    GETP(float, p_g, g_g); GETP(__half, p_op, g_op);
    GETP(__half, p_tw, g_tw); GETP(__half, p_ta, g_ta);
    GETP(__half, p_tv, g_tv); GETP(__half, p_tg, g_tg);
    GETP(unsigned, p_Wr, g_Wrp); GETP(unsigned, p_Wk, g_Wkp);
    GETP(unsigned, p_Wv, g_Wvp); GETP(unsigned, p_Wo, g_Wop);
    GETP(unsigned, p_w1, g_w1p); GETP(unsigned, p_a1, g_a1p);
    GETP(unsigned, p_v1, g_v1p); GETP(unsigned, p_g1, g_g1p);
    GETP(unsigned, p_w2, g_w2p); GETP(unsigned, p_a2, g_a2p);
    GETP(unsigned, p_v2, g_v2p); GETP(unsigned, p_g2, g_g2p);
#undef GETP

    static cudaStream_t s1 = nullptr;
    static cudaEvent_t evFork = nullptr, evW = nullptr, evM = nullptr, evJ = nullptr;
    if (!s1) {
        cudaStreamCreateWithFlags(&s1, cudaStreamNonBlocking);
        cudaEventCreateWithFlags(&evFork, cudaEventDisableTiming);
        cudaEventCreateWithFlags(&evW, cudaEventDisableTiming);
        cudaEventCreateWithFlags(&evM, cudaEventDisableTiming);
        cudaEventCreateWithFlags(&evJ, cudaEventDisableTiming);
    }

    // fork: side stream joins capture via event from capturing stream
    cudaEventRecord(evFork, 0);
    cudaStreamWaitEvent(s1, evFork, 0);

    // 0) weight pack prepass on SIDE stream (overlaps mix on main)
    {
        WP wp = {};
        const float* srcs[12] = {W_r, W_k, W_v, W_o, w1, a1, v1, g1, w2, a2, v2, g2};
        unsigned* dsts[12] = {p_Wr, p_Wk, p_Wv, p_Wo, p_w1, p_a1, p_v1, p_g1,
                              p_w2, p_a2, p_v2, p_g2};
        int K2d[12] = {Cn/2, Cn/2, Cn/2, Cn/2, Cn/2, Cn/2, Cn/2, Cn/2, 64, 64, 32, 128};
        int Nd[12]  = {Cn, Cn, Cn, Cn, 128, 128, 64, 256, Cn, Cn, Cn, Cn};
        int Ks[12]  = {Cn, Cn, Cn, Cn, Cn, Cn, Cn, Cn, 96, 96, 64, 256};
        int Ns[12]  = {Cn, Cn, Cn, Cn, 96, 96, 64, 256, Cn, Cn, Cn, Cn};
        int maxt = 0;
        for (int i = 0; i < 12; i++) {
            wp.src[i] = srcs[i]; wp.dst[i] = dsts[i];
            wp.K2d[i] = K2d[i]; wp.Nd[i] = Nd[i];
            wp.Ks[i] = Ks[i]; wp.Ns[i] = Ns[i];
            if (K2d[i] * Nd[i] > maxt) maxt = K2d[i] * Nd[i];
        }
        pack_w<<<dim3((maxt + 255) / 256, 12), 256, 0, s1>>>(wp);
        cudaEventRecord(evW, s1);
    }

    // 1) token shift + mixes on MAIN (half outputs)
    mix_kernel<<<(BTn * Cn / 4 + 255) / 256, 256>>>(
        (const float4*)x, (const float4*)x_r, (const float4*)x_w, (const float4*)x_k,
        (const float4*)x_v, (const float4*)x_a, (const float4*)x_g);
    cudaEventRecord(evM, 0);

    cudaStreamWaitEvent(0, evW, 0);
    cudaStreamWaitEvent(s1, evM, 0);

    constexpr int STG = 3, KT2 = 16;
    const int smemBig = STG * (128 * (KT2 + 4) + KT2 * (128 + 8)) * 4;  // 56832
    const int smemUp  = STG * (128 * (KT2 + 4) + KT2 * (64 + 8)) * 4;   // 44544
    cudaFuncSetAttribute(gemm_h<128, 128, 64, 64>,
                         cudaFuncAttributeMaxDynamicSharedMemorySize, smemBig);
    cudaFuncSetAttribute(gemm_h<128, 64, 64, 32>,
                         cudaFuncAttributeMaxDynamicSharedMemorySize, smemUp);

    // 2) r/k/v projections (main)
    {
        GH p = {};
        p.A[0] = p_xr; p.A[1] = p_xk; p.A[2] = p_xv;
        p.Bp[0] = p_Wr; p.Bp[1] = p_Wk; p.Bp[2] = p_Wv;
        p.C[0] = p_r;  p.C[1] = p_k;  p.C[2] = p_v;
        for (int z = 0; z < 3; z++) { p.N[z] = Cn; p.K[z] = Cn; p.act[z] = 0; p.outHalf[z] = 0; }
        gemm_h<128, 128, 64, 64><<<dim3(16, 16, 3), 128, smemBig>>>(p);
    }

    // 3a) LoRA ups (side stream)
    {
        GH p = {};
        p.A[0] = p_xw; p.A[1] = p_xa; p.A[2] = p_xv; p.A[3] = p_xg;
        p.Bp[0] = p_w1; p.Bp[1] = p_a1; p.Bp[2] = p_v1; p.Bp[3] = p_g1;
        p.C[0] = p_tw; p.C[1] = p_ta; p.C[2] = p_tv; p.C[3] = p_tg;
        p.N[0] = 128; p.N[1] = 128; p.N[2] = 64; p.N[3] = 256;
        for (int z = 0; z < 4; z++) { p.K[z] = Cn; p.outHalf[z] = 1; }
        p.act[0] = 1; p.act[1] = 0; p.act[2] = 0; p.act[3] = 2;
        gemm_h<128, 64, 64, 32><<<dim3(4, 16, 4), 128, smemUp, s1>>>(p);
    }

    // 3b) LoRA downs (side stream)
    {
        GH p = {};
        p.A[0] = p_tw; p.A[1] = p_ta; p.A[2] = p_tv; p.A[3] = p_tg;
        p.Bp[0] = p_w2; p.Bp[1] = p_a2; p.Bp[2] = p_v2; p.Bp[3] = p_g2;
        p.C[0] = p_w;  p.C[1] = p_za; p.C[2] = p_zv; p.C[3] = p_g;
        p.K[0] = 128; p.K[1] = 128; p.K[2] = 64; p.K[3] = 256;
        for (int z = 0; z < 4; z++) { p.N[z] = Cn; p.act[z] = 0; p.outHalf[z] = 0; }
        gemm_h<128, 128, 64, 64><<<dim3(16, 16, 4), 128, smemBig, s1>>>(p);
        cudaEventRecord(evJ, s1);
    }

    // join
    cudaStreamWaitEvent(0, evJ, 0);

    // 4) per-head elementwise -> packed scan operands
    ew2_kernel<<<BTn * Hn / 8, 256>>>(w0, a0, v0, k_k, k_a, vfirst);

    // 5) WKV7 scan (256 threads, 8 k's per thread)
    wkv7_scan<<<2 * Bn * Hn, 256>>>();

    // 6) groupnorm + residual + gate
    gn_kernel<<<BTn * Hn / 8, 256>>>(r_k, gnw, gnb);

    // 7) output projection
    {
        GH p = {};
        p.A[0] = p_op; p.Bp[0] = p_Wo; p.C[0] = out;
        p.N[0] = Cn; p.K[0] = Cn; p.act[0] = 0; p.outHalf[0] = 0;
        gemm_h<128, 128, 64, 64><<<dim3(16, 16, 1), 128, smemBig>>>(p);
    }
}

// round 15
// speedup vs baseline: 1.5806x; 1.5806x over previous
#include <cuda_runtime.h>
#include <cuda_fp16.h>
#include <math.h>

// Problem constants
#define Bn 2
#define Tn 1024
#define Cn 2048
#define Hn 32
#define Nn 64
#define BTn (Bn*Tn)

// ------------------------- scratch (static device globals) -------------------------
__device__ __half g_xr[BTn*Cn];
__device__ __half g_xw[BTn*Cn];
__device__ __half g_xk[BTn*Cn];
__device__ __half g_xv[BTn*Cn];
__device__ __half g_xa[BTn*Cn];
__device__ __half g_xg[BTn*Cn];
__device__ float g_r [BTn*Cn];
__device__ float g_k [BTn*Cn];
__device__ float g_v [BTn*Cn];
__device__ float g_w [BTn*Cn];
__device__ float g_za[BTn*Cn];
__device__ float g_zv[BTn*Cn];
__device__ float g_g [BTn*Cn];
__device__ float g_y [BTn*Cn];
__device__ __half g_op[BTn*Cn];
__device__ __half g_tw[BTn*128];
__device__ __half g_ta[BTn*128];
__device__ __half g_tv[BTn*64];
__device__ __half g_tg[BTn*256];
// packed scan operands: [B*H][T][6*64]  order: r,w,k,v,ah,bh
__device__ float g_pack[(size_t)Bn*Hn*Tn*384];
// half2-packed weights: [K/2][N] u32
__device__ unsigned g_Wrp[(Cn/2)*Cn];
__device__ unsigned g_Wkp[(Cn/2)*Cn];
__device__ unsigned g_Wvp[(Cn/2)*Cn];
__device__ unsigned g_Wop[(Cn/2)*Cn];
__device__ unsigned g_w1p[(Cn/2)*128];
__device__ unsigned g_a1p[(Cn/2)*128];
__device__ unsigned g_v1p[(Cn/2)*64];
__device__ unsigned g_g1p[(Cn/2)*256];
__device__ unsigned g_w2p[64*Cn];
__device__ unsigned g_a2p[64*Cn];
__device__ unsigned g_v2p[32*Cn];
__device__ unsigned g_g2p[128*Cn];

// ------------------------- helpers -------------------------
__device__ __forceinline__ void mma_h(float* d, const unsigned* a, const unsigned* b) {
    asm volatile(
        "mma.sync.aligned.m16n8k16.row.col.f32.f16.f16.f32 "
        "{%0,%1,%2,%3}, {%4,%5,%6,%7}, {%8,%9}, {%0,%1,%2,%3};"
        : "+f"(d[0]), "+f"(d[1]), "+f"(d[2]), "+f"(d[3])
        : "r"(a[0]), "r"(a[1]), "r"(a[2]), "r"(a[3]),
          "r"(b[0]), "r"(b[1]));
}

__device__ __forceinline__ void cp16(void* smem, const void* g) {
    unsigned saddr = (unsigned)__cvta_generic_to_shared(smem);
    asm volatile("cp.async.cg.shared.global [%0], [%1], 16;" :: "r"(saddr), "l"(g));
}
__device__ __forceinline__ void cp_commit() { asm volatile("cp.async.commit_group;" ::: "memory"); }
__device__ __forceinline__ void cp_wait1()  { asm volatile("cp.async.wait_group 1;" ::: "memory"); }

__device__ __forceinline__ float warp_sum(float v) {
#pragma unroll
    for (int o = 16; o > 0; o >>= 1) v += __shfl_xor_sync(0xffffffffu, v, o);
    return v;
}

__device__ __forceinline__ unsigned pack_h2(float lo, float hi) {
    __half2 h = __halves2half2(__float2half_rn(lo), __float2half_rn(hi));
    return *(unsigned*)&h;
}

// ------------------------- weight pack prepass (float -> half2-along-k) ------------
struct WP {
    const float* src[12];
    unsigned* dst[12];
    int K2d[12], Nd[12], Ks[12], Ns[12];
};
__global__ void pack_w(WP p) {
    int z = blockIdx.y;
    int i = blockIdx.x * blockDim.x + threadIdx.x;
    int tot = p.K2d[z] * p.Nd[z];
    if (i >= tot) return;
    int k2 = i / p.Nd[z], n = i % p.Nd[z];
    int k0 = 2 * k2, k1 = k0 + 1;
    float lo = 0.f, hi = 0.f;
    if (n < p.Ns[z]) {
        if (k0 < p.Ks[z]) lo = p.src[z][(size_t)k0 * p.Ns[z] + n];
        if (k1 < p.Ks[z]) hi = p.src[z][(size_t)k1 * p.Ns[z] + n];
    }
    p.dst[z][i] = pack_h2(lo, hi);
}

// ------------------------- batched 3-stage fp16 GEMM (m16n8k16, f32 accum) ---------
struct GH {
    const __half* A[4];
    const unsigned* Bp[4];
    void* C[4];
    int N[4];
    int K[4];
    int act[4];      // 0=none 1=tanh 2=sigmoid
    int outHalf[4];
};

template<int BM, int BN, int WM, int WN>
__global__ void __launch_bounds__((BM/WM)*(BN/WN)*32)
gemm_h(GH p) {
    constexpr int KT = 32;
    constexpr int KT2 = 16;
    constexpr int STG = 3;
    constexpr int WARPS_M = BM / WM;
    constexpr int WARPS_N = BN / WN;
    constexpr int NTHREADS = WARPS_M * WARPS_N * 32;
    constexpr int MT = WM / 16;
    constexpr int NT_ = WN / 8;
    constexpr int ASTR = KT2 + 4;
    constexpr int BSTR = BN + 8;

    extern __shared__ unsigned dsmg[];
    unsigned (*Asm)[BM][ASTR] = (unsigned(*)[BM][ASTR])dsmg;
    unsigned (*Bsm)[KT2][BSTR] = (unsigned(*)[KT2][BSTR])(dsmg + STG * BM * ASTR);

    const int z = blockIdx.z;
    const __half* A = p.A[z];
    const unsigned* B = p.Bp[z];
    const int N = p.N[z], K = p.K[z], act = p.act[z], oh = p.outHalf[z];
    const int bn = blockIdx.x * BN;
    if (bn >= N) return;
    const int bm = blockIdx.y * BM;

    const int tid = threadIdx.x;
    const int wid = tid >> 5, lane = tid & 31;
    const int gid = lane >> 2, tig = lane & 3;
    const int warp_m = wid / WARPS_N, warp_n = wid % WARPS_N;
    const int wm = warp_m * WM, wn = warp_n * WN;

    float acc[MT][NT_][4];
#pragma unroll
    for (int i = 0; i < MT; i++)
#pragma unroll
        for (int j = 0; j < NT_; j++)
#pragma unroll
            for (int q = 0; q < 4; q++) acc[i][j][q] = 0.f;

    auto load_stage = [&](int s, int kt) {
#pragma unroll
        for (int i = 0; i < (BM * 4) / NTHREADS; i++) {
            int id = tid + i * NTHREADS;
            int m = id >> 2, q = (id & 3) * 4;
            cp16(&Asm[s][m][q], A + (size_t)(bm + m) * K + kt * KT + q * 2);
        }
#pragma unroll
        for (int i = 0; i < (KT2 * BN / 4) / NTHREADS; i++) {
            int id = tid + i * NTHREADS;
            int kr = id / (BN / 4), nq = (id % (BN / 4)) * 4;
            cp16(&Bsm[s][kr][nq], B + (size_t)(kt * KT2 + kr) * N + bn + nq);
        }
    };

    const int nk = K / KT;
    load_stage(0, 0); cp_commit();
    load_stage(1, 1); cp_commit();

    int s = 0;
    for (int kt = 0; kt < nk; kt++) {
        cp_wait1();
        __syncthreads();
        if (kt + 2 < nk) load_stage((kt + 2) % STG, kt + 2);
        cp_commit();

#pragma unroll
        for (int kk2 = 0; kk2 < KT2; kk2 += 8) {
            unsigned af[MT][4], bf[NT_][2];
#pragma unroll
            for (int mt = 0; mt < MT; mt++) {
                int rm = wm + mt * 16 + gid;
                af[mt][0] = Asm[s][rm][kk2 + tig];
                af[mt][1] = Asm[s][rm + 8][kk2 + tig];
                af[mt][2] = Asm[s][rm][kk2 + tig + 4];
                af[mt][3] = Asm[s][rm + 8][kk2 + tig + 4];
            }
#pragma unroll
            for (int nt = 0; nt < NT_; nt++) {
                int cn = wn + nt * 8 + gid;
                bf[nt][0] = Bsm[s][kk2 + tig][cn];
                bf[nt][1] = Bsm[s][kk2 + tig + 4][cn];
            }
#pragma unroll
            for (int mt = 0; mt < MT; mt++)
#pragma unroll
                for (int nt = 0; nt < NT_; nt++)
                    mma_h(acc[mt][nt], af[mt], bf[nt]);
        }
        s = (s + 1 == STG) ? 0 : s + 1;
    }

#pragma unroll
    for (int mt = 0; mt < MT; mt++) {
#pragma unroll
        for (int nt = 0; nt < NT_; nt++) {
            int r0 = bm + wm + mt * 16 + gid;
            int c = bn + wn + nt * 8 + tig * 2;
            float v0 = acc[mt][nt][0], v1 = acc[mt][nt][1];
            float v2 = acc[mt][nt][2], v3 = acc[mt][nt][3];
            if (act == 1) {
                v0 = tanhf(v0); v1 = tanhf(v1); v2 = tanhf(v2); v3 = tanhf(v3);
            } else if (act == 2) {
                v0 = 1.f / (1.f + expf(-v0)); v1 = 1.f / (1.f + expf(-v1));
                v2 = 1.f / (1.f + expf(-v2)); v3 = 1.f / (1.f + expf(-v3));
            }
            if (oh) {
                __half* C = (__half*)p.C[z];
                *(unsigned*)(C + (size_t)r0 * N + c) = pack_h2(v0, v1);
                *(unsigned*)(C + (size_t)(r0 + 8) * N + c) = pack_h2(v2, v3);
            } else {
                float* C = (float*)p.C[z];
                *(float2*)(C + (size_t)r0 * N + c) = make_float2(v0, v1);
                *(float2*)(C + (size_t)(r0 + 8) * N + c) = make_float2(v2, v3);
            }
        }
    }
}

// ------------------------- token shift + 6 mixes (half outputs) --------------------
__global__ void mix_kernel(const float4* __restrict__ x,
                           const float4* __restrict__ cr, const float4* __restrict__ cw,
                           const float4* __restrict__ ck, const float4* __restrict__ cv,
                           const float4* __restrict__ ca, const float4* __restrict__ cg) {
    size_t i = (size_t)blockIdx.x * blockDim.x + threadIdx.x;
    constexpr size_t TOT = (size_t)BTn * Cn / 4;
    constexpr int C4 = Cn / 4;
    if (i >= TOT) return;
    int c = (int)(i % C4);
    size_t bt = i / C4;
    int t = (int)(bt % Tn);
    float4 xc = x[i];
    float4 prev = (t == 0) ? make_float4(0.f, 0.f, 0.f, 0.f) : x[i - C4];
    float4 dx = make_float4(prev.x - xc.x, prev.y - xc.y, prev.z - xc.z, prev.w - xc.w);
#define MIXO(dst, coef) { \
    float4 cc = coef[c]; \
    uint2 o; \
    o.x = pack_h2(fmaf(dx.x, cc.x, xc.x), fmaf(dx.y, cc.y, xc.y)); \
    o.y = pack_h2(fmaf(dx.z, cc.z, xc.z), fmaf(dx.w, cc.w, xc.w)); \
    ((uint2*)dst)[i] = o; }
    MIXO(g_xr, cr); MIXO(g_xw, cw); MIXO(g_xk, ck);
    MIXO(g_xv, cv); MIXO(g_xa, ca); MIXO(g_xg, cg);
#undef MIXO
}

// ------------------------- per-head elementwise stage 2 (warp per head) -----------
__global__ void __launch_bounds__(256) ew2_kernel(
        const float* __restrict__ w0, const float* __restrict__ a0,
        const float* __restrict__ v0, const float* __restrict__ kkw,
        const float* __restrict__ kaw, const float* __restrict__ vfirst) {
    int w = blockIdx.x * 8 + (threadIdx.x >> 5);
    int lane = threadIdx.x & 31;
    int bt = w / Hn, h = w % Hn;
    int b = bt / Tn, t = bt % Tn;
    size_t pb = ((size_t)(b * Hn + h) * Tn + t) * 384;
    size_t base = (size_t)bt * Cn + h * Nn;

    float kraw[2], kkp[2], av[2], vv[2], wv[2];
#pragma unroll
    for (int j = 0; j < 2; j++) {
        int n = lane + 32 * j;
        int c = h * Nn + n;
        size_t idx = base + n;
        kraw[j] = g_k[idx];
        kkp[j] = kraw[j] * kkw[c];
        av[j] = 1.f / (1.f + expf(-(a0[c] + g_za[idx])));
        float xw = -(w0[c] + g_w[idx]);
        float sp = (xw > 20.f) ? xw : log1pf(expf(xw));
        wv[j] = expf(-expf(-0.5f - sp));
        float vs = 1.f / (1.f + expf(-(v0[c] + g_zv[idx])));
        float vraw = g_v[idx];
        vv[j] = vraw + (vfirst[idx] - vraw) * vs;
    }
    float nrm2 = warp_sum(kkp[0] * kkp[0] + kkp[1] * kkp[1]);
    float inv = 1.f / fmaxf(sqrtf(nrm2), 1e-12f);

#pragma unroll
    for (int j = 0; j < 2; j++) {
        int n = lane + 32 * j;
        int c = h * Nn + n;
        size_t idx = base + n;
        float kkn = kkp[j] * inv;
        g_pack[pb +       n] = g_r[idx];
        g_pack[pb +  64 + n] = wv[j];
        g_pack[pb + 128 + n] = kraw[j] * (1.f + (av[j] - 1.f) * kaw[c]);
        g_pack[pb + 192 + n] = vv[j];
        g_pack[pb + 256 + n] = -kkn;
        g_pack[pb + 320 + n] = kkn * av[j];
    }
}

// ------------------------- WKV7 scan: 128 threads, 16-step groups, cp.async --------
// grid = 2*B*H blocks; block handles v in [vh*32, vh*32+32).
// Thread (v_local = tid>>2, kq = tid&3) owns S[v][16*kq .. 16*kq+15].
__global__ void __launch_bounds__(128) wkv7_scan() {
    const int bh = blockIdx.x >> 1;
    const int vh = blockIdx.x & 1;
    const int b = bh / Hn, h = bh % Hn;
    const int tid = threadIdx.x;
    const int v_local = tid >> 2;
    const int kq = tid & 3;
    const int v = vh * 32 + v_local;
    constexpr int GS = 16;

    float S[16];
#pragma unroll
    for (int i = 0; i < 16; i++) S[i] = 0.f;

    __shared__ float4 sm4[2][GS][96];   // 48 KB
    const float4* pk4 = (const float4*)(g_pack + (size_t)bh * Tn * 384);
    size_t ybase = (size_t)b * Tn * Cn + (size_t)h * Nn + v;

    auto load_group = [&](int buf, int g) {
#pragma unroll
        for (int i = 0; i < (GS * 96) / 128; i++) {
            int id = tid + i * 128;
            int st = id / 96, off = id % 96;
            cp16(&sm4[buf][st][off], pk4 + (size_t)(g * GS + st) * 96 + off);
        }
    };

    load_group(0, 0); cp_commit();
    load_group(1, 1); cp_commit();

    const int kb4 = kq * 4;
    constexpr int NG = Tn / GS;

    for (int g = 0; g < NG; g++) {
        cp_wait1();
        __syncthreads();
        const int buf = g & 1;

#pragma unroll
        for (int st = 0; st < GS; st++) {
            const float4* r4  = &sm4[buf][st][0  + kb4];
            const float4* w4  = &sm4[buf][st][16 + kb4];
            const float4* k4  = &sm4[buf][st][32 + kb4];
            const float4* ah4 = &sm4[buf][st][64 + kb4];
            const float4* bh4 = &sm4[buf][st][80 + kb4];
            const float vv = ((const float*)&sm4[buf][st][48])[v];

            float4 A0 = ah4[0], A1 = ah4[1], A2 = ah4[2], A3 = ah4[3];
            float sa0 = S[0] * A0.x, sa1 = S[4] * A1.x, sa2 = S[8] * A2.x, sa3 = S[12] * A3.x;
            sa0 = fmaf(S[1], A0.y, sa0); sa1 = fmaf(S[5], A1.y, sa1);
            sa2 = fmaf(S[9], A2.y, sa2); sa3 = fmaf(S[13], A3.y, sa3);
            sa0 = fmaf(S[2], A0.z, sa0); sa1 = fmaf(S[6], A1.z, sa1);
            sa2 = fmaf(S[10], A2.z, sa2); sa3 = fmaf(S[14], A3.z, sa3);
            sa0 = fmaf(S[3], A0.w, sa0); sa1 = fmaf(S[7], A1.w, sa1);
            sa2 = fmaf(S[11], A2.w, sa2); sa3 = fmaf(S[15], A3.w, sa3);
            float sa = (sa0 + sa1) + (sa2 + sa3);
            sa += __shfl_xor_sync(0xffffffffu, sa, 1);
            sa += __shfl_xor_sync(0xffffffffu, sa, 2);

            float y0 = 0.f, y1 = 0.f, y2 = 0.f, y3 = 0.f;
#pragma unroll
            for (int j = 0; j < 4; j++) {
                float4 W = w4[j], Bv = bh4[j], Kv = k4[j], R = r4[j];
                S[j*4+0] = fmaf(S[j*4+0], W.x, fmaf(sa, Bv.x, vv * Kv.x));
                S[j*4+1] = fmaf(S[j*4+1], W.y, fmaf(sa, Bv.y, vv * Kv.y));
                S[j*4+2] = fmaf(S[j*4+2], W.z, fmaf(sa, Bv.z, vv * Kv.z));
                S[j*4+3] = fmaf(S[j*4+3], W.w, fmaf(sa, Bv.w, vv * Kv.w));
                y0 = fmaf(S[j*4+0], R.x, y0);
                y1 = fmaf(S[j*4+1], R.y, y1);
                y2 = fmaf(S[j*4+2], R.z, y2);
                y3 = fmaf(S[j*4+3], R.w, y3);
            }
            float y = (y0 + y1) + (y2 + y3);
            y += __shfl_xor_sync(0xffffffffu, y, 1);
            y += __shfl_xor_sync(0xffffffffu, y, 2);
            if (kq == 0) g_y[ybase + (size_t)(g * GS + st) * Cn] = y;
        }

        __syncthreads();
        if (g + 2 < NG) load_group(buf, g + 2);
        cp_commit();
    }
}

// ------------------------- groupnorm + rk residual + gate (warp per head) ---------
__global__ void __launch_bounds__(256) gn_kernel(
        const float* __restrict__ r_k, const float* __restrict__ gnw,
        const float* __restrict__ gnb) {
    int w = blockIdx.x * 8 + (threadIdx.x >> 5);
    int lane = threadIdx.x & 31;
    int bt = w / Hn, h = w % Hn;
    int b = bt / Tn, t = bt % Tn;
    size_t pb = ((size_t)(b * Hn + h) * Tn + t) * 384;
    size_t base = (size_t)bt * Cn + h * Nn;

    float yv[2], rr[2], kk[2], vv[2];
#pragma unroll
    for (int j = 0; j < 2; j++) {
        int n = lane + 32 * j;
        yv[j] = g_y[base + n];
        rr[j] = g_pack[pb + n];
        kk[j] = g_pack[pb + 128 + n];
        vv[j] = g_pack[pb + 192 + n];
    }
    float mu = warp_sum(yv[0] + yv[1]) * (1.f / 64.f);
    float d0 = yv[0] - mu, d1 = yv[1] - mu;
    float var = warp_sum(d0 * d0 + d1 * d1) * (1.f / 64.f);
    float rs = rsqrtf(var + (float)(Nn * 1e-5));

    float dp0, dp1;
    {
        int c0 = h * Nn + lane, c1 = c0 + 32;
        dp0 = rr[0] * kk[0] * r_k[c0];
        dp1 = rr[1] * kk[1] * r_k[c1];
    }
    float dot = warp_sum(dp0 + dp1);

#pragma unroll
    for (int j = 0; j < 2; j++) {
        int n = lane + 32 * j;
        int c = h * Nn + n;
        size_t idx = base + n;
        float d = (j == 0) ? d0 : d1;
        float yn = d * rs * gnw[c] + gnb[c];
        g_op[idx] = __float2half_rn((yn + dot * vv[j]) * g_g[idx]);
    }
}

// ------------------------- launch -------------------------
extern "C" void kernel_launch(void* const* d_in, const int* in_sizes, int n_in,
                              void* d_out, int out_size) {
    (void)in_sizes; (void)n_in; (void)out_size;
    const float* x      = (const float*)d_in[0];
    const float* vfirst = (const float*)d_in[1];
    const float* x_r = (const float*)d_in[2];
    const float* x_w = (const float*)d_in[3];
    const float* x_k = (const float*)d_in[4];
    const float* x_v = (const float*)d_in[5];
    const float* x_a = (const float*)d_in[6];
    const float* x_g = (const float*)d_in[7];
    const float* w0  = (const float*)d_in[8];
    const float* w1  = (const float*)d_in[9];
    const float* w2  = (const float*)d_in[10];
    const float* a0  = (const float*)d_in[11];
    const float* a1  = (const float*)d_in[12];
    const float* a2  = (const float*)d_in[13];
    const float* v0  = (const float*)d_in[14];
    const float* v1  = (const float*)d_in[15];
    const float* v2  = (const float*)d_in[16];
    const float* g1  = (const float*)d_in[17];
    const float* g2  = (const float*)d_in[18];
    const float* k_k = (const float*)d_in[19];
    const float* k_a = (const float*)d_in[20];
    const float* r_k = (const float*)d_in[21];
    const float* W_r = (const float*)d_in[22];
    const float* W_k = (const float*)d_in[23];
    const float* W_v = (const float*)d_in[24];
    const float* W_o = (const float*)d_in[25];
    const float* gnw = (const float*)d_in[26];
    const float* gnb = (const float*)d_in[27];
    float* out = (float*)d_out;

#define GETP(T, name, sym) T* name; cudaGetSymbolAddress((void**)&name, sym)
    GETP(__half, p_xr, g_xr); GETP(__half, p_xw, g_xw); GETP(__half, p_xk, g_xk);
    GETP(__half, p_xv, g_xv); GETP(__half, p_xa, g_xa); GETP(__half, p_xg, g_xg);
    GETP(float, p_r, g_r); GETP(float, p_k, g_k); GETP(float, p_v, g_v);
    GETP(float, p_w, g_w); GETP(float, p_za, g_za); GETP(float, p_zv, g_zv);
    GETP(float, p_g, g_g); GETP(__half, p_op, g_op);
    GETP(__half, p_tw, g_tw); GETP(__half, p_ta, g_ta);
    GETP(__half, p_tv, g_tv); GETP(__half, p_tg, g_tg);
    GETP(unsigned, p_Wr, g_Wrp); GETP(unsigned, p_Wk, g_Wkp);
    GETP(unsigned, p_Wv, g_Wvp); GETP(unsigned, p_Wo, g_Wop);
    GETP(unsigned, p_w1, g_w1p); GETP(unsigned, p_a1, g_a1p);
    GETP(unsigned, p_v1, g_v1p); GETP(unsigned, p_g1, g_g1p);
    GETP(unsigned, p_w2, g_w2p); GETP(unsigned, p_a2, g_a2p);
    GETP(unsigned, p_v2, g_v2p); GETP(unsigned, p_g2, g_g2p);
#undef GETP

    static cudaStream_t s1 = nullptr;
    static cudaEvent_t evFork = nullptr, evW = nullptr, evM = nullptr, evJ = nullptr;
    if (!s1) {
        cudaStreamCreateWithFlags(&s1, cudaStreamNonBlocking);
        cudaEventCreateWithFlags(&evFork, cudaEventDisableTiming);
        cudaEventCreateWithFlags(&evW, cudaEventDisableTiming);
        cudaEventCreateWithFlags(&evM, cudaEventDisableTiming);
        cudaEventCreateWithFlags(&evJ, cudaEventDisableTiming);
    }

    // fork: side stream joins capture via event from capturing stream
    cudaEventRecord(evFork, 0);
    cudaStreamWaitEvent(s1, evFork, 0);

    // 0) weight pack prepass on SIDE stream (overlaps mix on main)
    {
        WP wp = {};
        const float* srcs[12] = {W_r, W_k, W_v, W_o, w1, a1, v1, g1, w2, a2, v2, g2};
        unsigned* dsts[12] = {p_Wr, p_Wk, p_Wv, p_Wo, p_w1, p_a1, p_v1, p_g1,
                              p_w2, p_a2, p_v2, p_g2};
        int K2d[12] = {Cn/2, Cn/2, Cn/2, Cn/2, Cn/2, Cn/2, Cn/2, Cn/2, 64, 64, 32, 128};
        int Nd[12]  = {Cn, Cn, Cn, Cn, 128, 128, 64, 256, Cn, Cn, Cn, Cn};
        int Ks[12]  = {Cn, Cn, Cn, Cn, Cn, Cn, Cn, Cn, 96, 96, 64, 256};
        int Ns[12]  = {Cn, Cn, Cn, Cn, 96, 96, 64, 256, Cn, Cn, Cn, Cn};
        int maxt = 0;
        for (int i = 0; i < 12; i++) {
            wp.src[i] = srcs[i]; wp.dst[i] = dsts[i];
            wp.K2d[i] = K2d[i]; wp.Nd[i] = Nd[i];
            wp.Ks[i] = Ks[i]; wp.Ns[i] = Ns[i];
            if (K2d[i] * Nd[i] > maxt) maxt = K2d[i] * Nd[i];
        }
        pack_w<<<dim3((maxt + 255) / 256, 12), 256, 0, s1>>>(wp);
        cudaEventRecord(evW, s1);
    }

    // 1) token shift + mixes on MAIN (half outputs)
    mix_kernel<<<(BTn * Cn / 4 + 255) / 256, 256>>>(
        (const float4*)x, (const float4*)x_r, (const float4*)x_w, (const float4*)x_k,
        (const float4*)x_v, (const float4*)x_a, (const float4*)x_g);
    cudaEventRecord(evM, 0);

    cudaStreamWaitEvent(0, evW, 0);
    cudaStreamWaitEvent(s1, evM, 0);

    constexpr int STG = 3, KT2 = 16;
    const int smemBig = STG * (128 * (KT2 + 4) + KT2 * (128 + 8)) * 4;  // 56832
    const int smemUp  = STG * (128 * (KT2 + 4) + KT2 * (64 + 8)) * 4;   // 44544
    cudaFuncSetAttribute(gemm_h<128, 128, 64, 64>,
                         cudaFuncAttributeMaxDynamicSharedMemorySize, smemBig);
    cudaFuncSetAttribute(gemm_h<128, 64, 64, 32>,
                         cudaFuncAttributeMaxDynamicSharedMemorySize, smemUp);

    // 2) r/k/v projections (main)
    {
        GH p = {};
        p.A[0] = p_xr; p.A[1] = p_xk; p.A[2] = p_xv;
        p.Bp[0] = p_Wr; p.Bp[1] = p_Wk; p.Bp[2] = p_Wv;
        p.C[0] = p_r;  p.C[1] = p_k;  p.C[2] = p_v;
        for (int z = 0; z < 3; z++) { p.N[z] = Cn; p.K[z] = Cn; p.act[z] = 0; p.outHalf[z] = 0; }
        gemm_h<128, 128, 64, 64><<<dim3(16, 16, 3), 128, smemBig>>>(p);
    }

    // 3a) LoRA ups (side stream)
    {
        GH p = {};
        p.A[0] = p_xw; p.A[1] = p_xa; p.A[2] = p_xv; p.A[3] = p_xg;
        p.Bp[0] = p_w1; p.Bp[1] = p_a1; p.Bp[2] = p_v1; p.Bp[3] = p_g1;
        p.C[0] = p_tw; p.C[1] = p_ta; p.C[2] = p_tv; p.C[3] = p_tg;
        p.N[0] = 128; p.N[1] = 128; p.N[2] = 64; p.N[3] = 256;
        for (int z = 0; z < 4; z++) { p.K[z] = Cn; p.outHalf[z] = 1; }
        p.act[0] = 1; p.act[1] = 0; p.act[2] = 0; p.act[3] = 2;
        gemm_h<128, 64, 64, 32><<<dim3(4, 16, 4), 128, smemUp, s1>>>(p);
    }

    // 3b) LoRA downs (side stream)
    {
        GH p = {};
        p.A[0] = p_tw; p.A[1] = p_ta; p.A[2] = p_tv; p.A[3] = p_tg;
        p.Bp[0] = p_w2; p.Bp[1] = p_a2; p.Bp[2] = p_v2; p.Bp[3] = p_g2;
        p.C[0] = p_w;  p.C[1] = p_za; p.C[2] = p_zv; p.C[3] = p_g;
        p.K[0] = 128; p.K[1] = 128; p.K[2] = 64; p.K[3] = 256;
        for (int z = 0; z < 4; z++) { p.N[z] = Cn; p.act[z] = 0; p.outHalf[z] = 0; }
        gemm_h<128, 128, 64, 64><<<dim3(16, 16, 4), 128, smemBig, s1>>>(p);
        cudaEventRecord(evJ, s1);
    }

    // join
    cudaStreamWaitEvent(0, evJ, 0);

    // 4) per-head elementwise -> packed scan operands
    ew2_kernel<<<BTn * Hn / 8, 256>>>(w0, a0, v0, k_k, k_a, vfirst);

    // 5) WKV7 scan (128 threads, 16-step groups)
    wkv7_scan<<<2 * Bn * Hn, 128>>>();

    // 6) groupnorm + residual + gate
    gn_kernel<<<BTn * Hn / 8, 256>>>(r_k, gnw, gnb);

    // 7) output projection
    {
        GH p = {};
        p.A[0] = p_op; p.Bp[0] = p_Wo; p.C[0] = out;
        p.N[0] = Cn; p.K[0] = Cn; p.act[0] = 0; p.outHalf[0] = 0;
        gemm_h<128, 128, 64, 64><<<dim3(16, 16, 1), 128, smemBig>>>(p);
    }
}